// round 1
// baseline (speedup 1.0000x reference)
#include <cuda_runtime.h>
#include <math.h>

#define Bq 16
#define NN 1024
#define DD 256
#define HH 128
#define LL 2

// ---------------- scratch (device globals; no allocation) ----------------
__device__ float g_gate[Bq * NN];
__device__ float g_Ain [Bq * NN * NN];   // row-gated blend  (used as-is,   NN gemm)
__device__ float g_Aout[Bq * NN * NN];   // col-gated blend  (used as M^T,  TN gemm)
__device__ float g_Yin [Bq * NN * DD];
__device__ float g_Yout[Bq * NN * DD];
__device__ float g_xmid[Bq * NN * DD];
__device__ float g_h   [Bq * NN * DD];   // 2H == D

// ---------------- K1: per-node refine gate ----------------
__global__ void gate_kernel(const float* __restrict__ x_ext, int use_mid,
                            const float* __restrict__ rg) {
    const float* x = use_mid ? g_xmid : x_ext;
    int warp = (blockIdx.x * blockDim.x + threadIdx.x) >> 5;
    int lane = threadIdx.x & 31;
    if (warp >= Bq * NN) return;
    const float* xp = x + (size_t)warp * DD;
    float s = 0.f;
    #pragma unroll
    for (int d = lane; d < DD; d += 32) s += xp[d] * rg[d];
    #pragma unroll
    for (int off = 16; off; off >>= 1) s += __shfl_xor_sync(0xffffffffu, s, off);
    if (lane == 0) g_gate[warp] = 1.f / (1.f + expf(-s));
}

// ---------------- K2: build blended adjacencies (fully coalesced) ----------------
// g_Ain [b,i,j] = g[b,i]*dep + (1-g[b,i])*lat        (A_in,  used directly)
// g_Aout[b,i,j] = g[b,j]*dep + (1-g[b,j])*lat        (M, so A_out = M^T)
__global__ void buildA_kernel(const float* __restrict__ dep, const float* __restrict__ lat) {
    size_t idx = (size_t)blockIdx.x * blockDim.x + threadIdx.x;   // over Bq*NN*NN/4
    size_t total = (size_t)Bq * NN * NN / 4;
    if (idx >= total) return;
    size_t e = idx * 4;
    int j  = (int)(e % NN);
    size_t bi = e / NN;
    int i  = (int)(bi % NN);
    int b  = (int)(bi / NN);
    float gi = g_gate[b * NN + i];
    const float* grow = g_gate + b * NN;
    float gj0 = grow[j + 0], gj1 = grow[j + 1], gj2 = grow[j + 2], gj3 = grow[j + 3];
    float4 dv = *(const float4*)(dep + e);
    float4 lv = *(const float4*)(lat + e);
    float4 ain, aout;
    ain.x = fmaf(gi, dv.x - lv.x, lv.x);
    ain.y = fmaf(gi, dv.y - lv.y, lv.y);
    ain.z = fmaf(gi, dv.z - lv.z, lv.z);
    ain.w = fmaf(gi, dv.w - lv.w, lv.w);
    aout.x = fmaf(gj0, dv.x - lv.x, lv.x);
    aout.y = fmaf(gj1, dv.y - lv.y, lv.y);
    aout.z = fmaf(gj2, dv.z - lv.z, lv.z);
    aout.w = fmaf(gj3, dv.w - lv.w, lv.w);
    *(float4*)(g_Ain  + e) = ain;
    *(float4*)(g_Aout + e) = aout;
}

// ---------------- K3: batched SGEMM  Y = A @ x  (or A^T @ x) ----------------
// M = NN, K = NN, Ncols = DD. 64x64x16 tile, 256 threads, 4x4 per thread.
template <bool TRANS>
__global__ __launch_bounds__(256) void adj_gemm_kernel(const float* __restrict__ x_ext, int use_mid) {
    const float* A = TRANS ? g_Aout : g_Ain;
    float*       Y = TRANS ? g_Yout : g_Yin;
    const float* X = use_mid ? g_xmid : x_ext;

    __shared__ float sA[16][64];
    __shared__ float sX[16][64];

    int b  = blockIdx.z;
    int m0 = blockIdx.y * 64;
    int n0 = blockIdx.x * 64;
    const float* Ab = A + (size_t)b * NN * NN;
    const float* Xb = X + (size_t)b * NN * DD;
    float*       Yb = Y + (size_t)b * NN * DD;

    int tid = threadIdx.x;
    int tx = tid & 15, ty = tid >> 4;

    float acc[4][4] = {};

    for (int k0 = 0; k0 < NN; k0 += 16) {
        if (TRANS) {
            // A stored [k][m]; coalesced direct load
            int e = tid * 4; int k = e >> 6; int m = e & 63;
            float4 v = *(const float4*)(Ab + (size_t)(k0 + k) * NN + m0 + m);
            *(float4*)(&sA[k][m]) = v;
        } else {
            // A stored [m][k]; load 4 contiguous k, scatter-transpose into smem
            int e = tid * 4; int m = e >> 4; int k = e & 15;
            float4 v = *(const float4*)(Ab + (size_t)(m0 + m) * NN + k0 + k);
            sA[k + 0][m] = v.x; sA[k + 1][m] = v.y; sA[k + 2][m] = v.z; sA[k + 3][m] = v.w;
        }
        {
            int e = tid * 4; int k = e >> 6; int n = e & 63;
            float4 v = *(const float4*)(Xb + (size_t)(k0 + k) * DD + n0 + n);
            *(float4*)(&sX[k][n]) = v;
        }
        __syncthreads();
        #pragma unroll
        for (int k = 0; k < 16; k++) {
            float4 a4 = *(const float4*)(&sA[k][ty * 4]);
            float4 x4 = *(const float4*)(&sX[k][tx * 4]);
            float ar[4] = {a4.x, a4.y, a4.z, a4.w};
            float xr[4] = {x4.x, x4.y, x4.z, x4.w};
            #pragma unroll
            for (int u = 0; u < 4; u++)
                #pragma unroll
                for (int v = 0; v < 4; v++)
                    acc[u][v] = fmaf(ar[u], xr[v], acc[u][v]);
        }
        __syncthreads();
    }

    #pragma unroll
    for (int u = 0; u < 4; u++) {
        int row = m0 + ty * 4 + u;
        float4 o = {acc[u][0], acc[u][1], acc[u][2], acc[u][3]};
        *(float4*)(Yb + (size_t)row * DD + n0 + tx * 4) = o;
    }
}

// ---------------- K4: gcn gate + residual add (in place on Yin/Yout) ----------------
__global__ void gcn_gate_kernel(const float* __restrict__ x_ext, int use_mid,
                                const float* __restrict__ Wgi, const float* __restrict__ bgi_p,
                                const float* __restrict__ Wgo, const float* __restrict__ bgo_p) {
    const float* x = use_mid ? g_xmid : x_ext;
    int warp = (blockIdx.x * blockDim.x + threadIdx.x) >> 5;
    int lane = threadIdx.x & 31;
    if (warp >= Bq * NN) return;
    size_t base = (size_t)warp * DD;
    float si = 0.f, so = 0.f;
    #pragma unroll
    for (int d = lane; d < DD; d += 32) {
        si += g_Yin [base + d] * Wgi[d];
        so += g_Yout[base + d] * Wgo[d];
    }
    #pragma unroll
    for (int off = 16; off; off >>= 1) {
        si += __shfl_xor_sync(0xffffffffu, si, off);
        so += __shfl_xor_sync(0xffffffffu, so, off);
    }
    float gi = 1.f / (1.f + expf(-si));
    float go = 1.f / (1.f + expf(-so));
    float bgi = bgi_p[0], bgo = bgo_p[0];
    #pragma unroll
    for (int d = lane; d < DD; d += 32) {
        float xv = x[base + d];
        g_Yin [base + d] = g_Yin [base + d] * gi + bgi + xv;  // s_in  = Ax_in  + x
        g_Yout[base + d] = g_Yout[base + d] * go + bgo + xv;  // s_out = Ax_out + x
    }
}

// ---------------- K5: fc GEMM  h[:, sel*H + c] = S @ W^T + 2*b ----------------
// M = Bq*NN, K = DD, Ncols = HH. NT gemm (both K-contiguous). 64x64x16 tile.
__global__ __launch_bounds__(256) void fc_gemm_kernel(const float* __restrict__ Wi, const float* __restrict__ bi,
                                                      const float* __restrict__ Wo, const float* __restrict__ bo) {
    int sel = blockIdx.z;
    const float* S    = sel ? g_Yout : g_Yin;
    const float* W    = sel ? Wo : Wi;
    const float* bias = sel ? bo : bi;

    __shared__ float sS[16][64];
    __shared__ float sW[16][64];

    int m0 = blockIdx.y * 64;
    int n0 = blockIdx.x * 64;
    int tid = threadIdx.x;
    int tx = tid & 15, ty = tid >> 4;

    float acc[4][4] = {};

    for (int k0 = 0; k0 < DD; k0 += 16) {
        {
            int e = tid * 4; int m = e >> 4; int k = e & 15;
            float4 v = *(const float4*)(S + (size_t)(m0 + m) * DD + k0 + k);
            sS[k + 0][m] = v.x; sS[k + 1][m] = v.y; sS[k + 2][m] = v.z; sS[k + 3][m] = v.w;
        }
        {
            int e = tid * 4; int n = e >> 4; int k = e & 15;
            float4 v = *(const float4*)(W + (size_t)(n0 + n) * DD + k0 + k);
            sW[k + 0][n] = v.x; sW[k + 1][n] = v.y; sW[k + 2][n] = v.z; sW[k + 3][n] = v.w;
        }
        __syncthreads();
        #pragma unroll
        for (int k = 0; k < 16; k++) {
            float4 a4 = *(const float4*)(&sS[k][ty * 4]);
            float4 w4 = *(const float4*)(&sW[k][tx * 4]);
            float ar[4] = {a4.x, a4.y, a4.z, a4.w};
            float wr[4] = {w4.x, w4.y, w4.z, w4.w};
            #pragma unroll
            for (int u = 0; u < 4; u++)
                #pragma unroll
                for (int v = 0; v < 4; v++)
                    acc[u][v] = fmaf(ar[u], wr[v], acc[u][v]);
        }
        __syncthreads();
    }

    #pragma unroll
    for (int u = 0; u < 4; u++) {
        int row = m0 + ty * 4 + u;
        #pragma unroll
        for (int v = 0; v < 4; v++) {
            int col = n0 + tx * 4 + v;
            g_h[(size_t)row * (2 * HH) + sel * HH + col] = acc[u][v] + 2.f * bias[col];
        }
    }
}

// ---------------- K6: LayerNorm(2H) + exact GELU ----------------
__global__ void ln_gelu_kernel(const float* __restrict__ gw, const float* __restrict__ bw,
                               float* __restrict__ out_ext, int to_mid) {
    float* out = to_mid ? g_xmid : out_ext;
    int node = blockIdx.x;
    int t = threadIdx.x;
    float v = g_h[(size_t)node * DD + t];

    float s = v, s2 = v * v;
    #pragma unroll
    for (int off = 16; off; off >>= 1) {
        s  += __shfl_xor_sync(0xffffffffu, s,  off);
        s2 += __shfl_xor_sync(0xffffffffu, s2, off);
    }
    __shared__ float red[2][8];
    int w = t >> 5, lane = t & 31;
    if (lane == 0) { red[0][w] = s; red[1][w] = s2; }
    __syncthreads();
    s = 0.f; s2 = 0.f;
    #pragma unroll
    for (int i = 0; i < 8; i++) { s += red[0][i]; s2 += red[1][i]; }

    float mu  = s  * (1.f / DD);
    float var = s2 * (1.f / DD) - mu * mu;
    float r   = rsqrtf(var + 1e-5f);
    float hn  = (v - mu) * r * gw[t] + bw[t];
    out[(size_t)node * DD + t] = 0.5f * hn * (1.f + erff(hn * 0.70710678118654752f));
}

// ---------------- host launcher ----------------
extern "C" void kernel_launch(void* const* d_in, const int* in_sizes, int n_in,
                              void* d_out, int out_size) {
    (void)in_sizes; (void)n_in; (void)out_size;
    const float* x0  = (const float*)d_in[0];
    const float* lat = (const float*)d_in[1];
    const float* dep = (const float*)d_in[2];
    const float* rg  = (const float*)d_in[3];
    const float* Wgi = (const float*)d_in[4];
    const float* bgi = (const float*)d_in[5];
    const float* Wgo = (const float*)d_in[6];
    const float* bgo = (const float*)d_in[7];
    const float* Wi  = (const float*)d_in[8];
    const float* bi  = (const float*)d_in[9];
    const float* Wo  = (const float*)d_in[10];
    const float* bo  = (const float*)d_in[11];
    const float* lng = (const float*)d_in[12];
    const float* lnb = (const float*)d_in[13];
    float* out = (float*)d_out;

    const int nodeWarpBlocks = (Bq * NN * 32) / 256;          // 2048
    const size_t buildElems  = (size_t)Bq * NN * NN / 4;
    const int buildBlocks    = (int)((buildElems + 255) / 256);

    for (int l = 0; l < LL; l++) {
        int use_mid = (l != 0);
        int to_mid  = (l != LL - 1);

        gate_kernel<<<nodeWarpBlocks, 256>>>(x0, use_mid, rg + l * DD);
        buildA_kernel<<<buildBlocks, 256>>>(dep, lat);

        dim3 gAdj(DD / 64, NN / 64, Bq);
        adj_gemm_kernel<false><<<gAdj, 256>>>(x0, use_mid);
        adj_gemm_kernel<true ><<<gAdj, 256>>>(x0, use_mid);

        gcn_gate_kernel<<<nodeWarpBlocks, 256>>>(x0, use_mid,
                                                 Wgi + l * DD, bgi + l,
                                                 Wgo + l * DD, bgo + l);

        dim3 gFc(HH / 64, (Bq * NN) / 64, 2);
        fc_gemm_kernel<<<gFc, 256>>>(Wi + (size_t)l * HH * DD, bi + l * HH,
                                     Wo + (size_t)l * HH * DD, bo + l * HH);

        ln_gelu_kernel<<<Bq * NN, 256>>>(lng + l * 2 * HH, lnb + l * 2 * HH,
                                         out, to_mid);
    }
}

// round 3
// speedup vs baseline: 2.5384x; 2.5384x over previous
#include <cuda_runtime.h>
#include <math.h>
#include <stdint.h>

#define Bq 16
#define NN 1024
#define DD 256
#define HH 128
#define LL 2

// ---------------- scratch (device globals; no allocation) ----------------
__device__ __align__(128) float g_gate[Bq * NN];
__device__ __align__(128) float g_Ain [Bq * NN * NN];   // row-major A_in  (tf32-rounded)
__device__ __align__(128) float g_Aout[Bq * NN * NN];   // row-major A_out (tf32-rounded)
__device__ __align__(128) float g_Xt  [Bq * DD * NN];   // x^T [b,d,k]     (tf32-rounded)
__device__ __align__(128) float g_Yin [Bq * NN * DD];
__device__ __align__(128) float g_Yout[Bq * NN * DD];
__device__ __align__(128) float g_xmid[Bq * NN * DD];
__device__ __align__(128) float g_h   [Bq * NN * DD];   // 2H == D

// ---------------- helpers ----------------
__device__ __forceinline__ uint32_t smem_u32(const void* p) {
    uint32_t a;
    asm("{ .reg .u64 t; cvta.to.shared.u64 t, %1; cvt.u32.u64 %0, t; }" : "=r"(a) : "l"(p));
    return a;
}
__device__ __forceinline__ float tf32r(float x) {
    uint32_t r;
    asm("cvt.rna.tf32.f32 %0, %1;" : "=r"(r) : "f"(x));
    return __uint_as_float(r);
}
__device__ __forceinline__ void cp16(uint32_t dst, const float* src) {
    asm volatile("cp.async.cg.shared.global [%0], [%1], 16;" :: "r"(dst), "l"(src) : "memory");
}
#define CP_COMMIT() asm volatile("cp.async.commit_group;" ::: "memory")
#define CP_WAIT1()  asm volatile("cp.async.wait_group 1;" ::: "memory")
#define CP_WAIT0()  asm volatile("cp.async.wait_group 0;" ::: "memory")

#define MMA4(D, A, B) \
    asm volatile("mma.sync.aligned.m16n8k8.row.col.f32.tf32.tf32.f32 " \
        "{%0,%1,%2,%3}, {%4,%5,%6,%7}, {%8,%9}, {%0,%1,%2,%3};" \
        : "+f"((D)[0]), "+f"((D)[1]), "+f"((D)[2]), "+f"((D)[3]) \
        : "r"((A)[0]), "r"((A)[1]), "r"((A)[2]), "r"((A)[3]), \
          "r"((B)[0]), "r"((B)[1]))

// smem tile geometry: 128 rows x 32 k, padded stride 36 floats
#define TSTRIDE 36
#define TILE_F (128 * TSTRIDE)   // 4608 floats

// ---------------- K1: per-node refine gate ----------------
__global__ void gate_kernel(const float* __restrict__ x_ext, int use_mid,
                            const float* __restrict__ rg) {
    const float* x = use_mid ? g_xmid : x_ext;
    int warp = (blockIdx.x * blockDim.x + threadIdx.x) >> 5;
    int lane = threadIdx.x & 31;
    if (warp >= Bq * NN) return;
    const float* xp = x + (size_t)warp * DD;
    float s = 0.f;
    #pragma unroll
    for (int d = lane; d < DD; d += 32) s += xp[d] * rg[d];
    #pragma unroll
    for (int off = 16; off; off >>= 1) s += __shfl_xor_sync(0xffffffffu, s, off);
    if (lane == 0) g_gate[warp] = 1.f / (1.f + expf(-s));
}

// ---------------- K2: build both adjacencies row-major (tiled transpose), tf32-rounded ----------------
__global__ void buildA2_kernel(const float* __restrict__ dep, const float* __restrict__ lat) {
    __shared__ float sd[32][33], sl[32][33];
    int b  = blockIdx.z;
    int i0 = blockIdx.y * 32;
    int j0 = blockIdx.x * 32;
    int tx = threadIdx.x, ty = threadIdx.y;
    const float* gb  = g_gate + b * NN;
    const float* dpb = dep + (size_t)b * NN * NN;
    const float* ltb = lat + (size_t)b * NN * NN;
    #pragma unroll
    for (int u = 0; u < 4; ++u) {
        int r = ty + 8 * u;
        sd[r][tx] = dpb[(size_t)(i0 + r) * NN + j0 + tx];
        sl[r][tx] = ltb[(size_t)(i0 + r) * NN + j0 + tx];
    }
    __syncthreads();
    size_t base = (size_t)b * NN * NN;
    #pragma unroll
    for (int u = 0; u < 4; ++u) {
        int r = ty + 8 * u;
        float gi = gb[i0 + r];
        float d = sd[r][tx], l = sl[r][tx];
        g_Ain[base + (size_t)(i0 + r) * NN + j0 + tx] = tf32r(fmaf(gi, d - l, l));
    }
    #pragma unroll
    for (int u = 0; u < 4; ++u) {
        int r = ty + 8 * u;                  // local j index
        float gj = gb[j0 + r];
        float d = sd[tx][r], l = sl[tx][r];  // dep[i0+tx][j0+r]
        g_Aout[base + (size_t)(j0 + r) * NN + i0 + tx] = tf32r(fmaf(gj, d - l, l));
    }
}

// ---------------- K3: transpose x -> Xt [b,d,k], tf32-rounded ----------------
__global__ void xt_kernel(const float* __restrict__ x_ext, int use_mid) {
    __shared__ float s[32][33];
    const float* x = use_mid ? g_xmid : x_ext;
    int b  = blockIdx.z;
    int k0 = blockIdx.y * 32;
    int d0 = blockIdx.x * 32;
    int tx = threadIdx.x, ty = threadIdx.y;
    const float* xb = x + (size_t)b * NN * DD;
    float* xtb = g_Xt + (size_t)b * DD * NN;
    #pragma unroll
    for (int u = 0; u < 4; ++u)
        s[ty + 8 * u][tx] = xb[(size_t)(k0 + ty + 8 * u) * DD + d0 + tx];
    __syncthreads();
    #pragma unroll
    for (int u = 0; u < 4; ++u)
        xtb[(size_t)(d0 + ty + 8 * u) * NN + k0 + tx] = tf32r(s[tx][ty + 8 * u]);
}

// ---------------- K4: tf32 mma.sync GEMM  Y = A @ x ----------------
// grid (nb=2, mb=8, z=b*2+sel). CTA tile 128x128, K-step 32, double-buffered cp.async.
#define ADJ_SMEM (2 * 2 * TILE_F * 4)   // 73728 bytes

__global__ void __launch_bounds__(256, 2) adj_mma_kernel() {
    extern __shared__ float dynf[];
    const int tid  = threadIdx.x;
    const int lane = tid & 31, warp = tid >> 5;
    const int wm = warp & 1, wn = warp >> 1;   // 2 x 4 warp grid
    const int nb = blockIdx.x, mb = blockIdx.y;
    const int b = blockIdx.z >> 1, sel = blockIdx.z & 1;

    const float* A  = (sel ? g_Aout : g_Ain) + (size_t)b * NN * NN + (size_t)mb * 128 * NN;
    const float* Bx = g_Xt + (size_t)b * DD * NN + (size_t)nb * 128 * NN;
    float*       Y  = (sel ? g_Yout : g_Yin) + (size_t)b * NN * DD;

    const uint32_t sbase = smem_u32(dynf);
    const int r = lane >> 2, c = lane & 3;

    float d[4][4][4] = {};

    // ---- prologue: stage 0 ----
    {
        #pragma unroll
        for (int u = 0; u < 4; ++u) {
            int e = tid + 256 * u; int row = e >> 3; int kq = (e & 7) << 2;
            cp16(sbase + (uint32_t)(row * TSTRIDE + kq) * 4,          A  + (size_t)row * NN + kq);
            cp16(sbase + (uint32_t)(TILE_F + row * TSTRIDE + kq) * 4, Bx + (size_t)row * NN + kq);
        }
        CP_COMMIT();
    }

    const int KT = NN / 32;
    for (int kt = 0; kt < KT; ++kt) {
        if (kt + 1 < KT) {
            uint32_t db = sbase + (uint32_t)(((kt + 1) & 1) * 2 * TILE_F) * 4;
            int k0 = (kt + 1) * 32;
            #pragma unroll
            for (int u = 0; u < 4; ++u) {
                int e = tid + 256 * u; int row = e >> 3; int kq = (e & 7) << 2;
                cp16(db + (uint32_t)(row * TSTRIDE + kq) * 4,          A  + (size_t)row * NN + k0 + kq);
                cp16(db + (uint32_t)(TILE_F + row * TSTRIDE + kq) * 4, Bx + (size_t)row * NN + k0 + kq);
            }
            CP_COMMIT();
            CP_WAIT1();
        } else {
            CP_WAIT0();
        }
        __syncthreads();

        const float* As = dynf + (kt & 1) * 2 * TILE_F;
        const float* Bs = As + TILE_F;
        #pragma unroll
        for (int kk = 0; kk < 32; kk += 8) {
            uint32_t a[4][4], bf[4][2];
            #pragma unroll
            for (int fm = 0; fm < 4; ++fm) {
                int m = wm * 64 + fm * 16 + r;
                a[fm][0] = __float_as_uint(As[m * TSTRIDE + kk + c]);
                a[fm][1] = __float_as_uint(As[(m + 8) * TSTRIDE + kk + c]);
                a[fm][2] = __float_as_uint(As[m * TSTRIDE + kk + c + 4]);
                a[fm][3] = __float_as_uint(As[(m + 8) * TSTRIDE + kk + c + 4]);
            }
            #pragma unroll
            for (int fn = 0; fn < 4; ++fn) {
                int n = wn * 32 + fn * 8 + r;
                bf[fn][0] = __float_as_uint(Bs[n * TSTRIDE + kk + c]);
                bf[fn][1] = __float_as_uint(Bs[n * TSTRIDE + kk + c + 4]);
            }
            #pragma unroll
            for (int fm = 0; fm < 4; ++fm)
                #pragma unroll
                for (int fn = 0; fn < 4; ++fn)
                    MMA4(d[fm][fn], a[fm], bf[fn]);
        }
        __syncthreads();
    }

    // ---- epilogue: raw Ax out ----
    const int c2 = (lane & 3) * 2;
    #pragma unroll
    for (int fm = 0; fm < 4; ++fm) {
        int row = mb * 128 + wm * 64 + fm * 16 + r;
        float* y0 = Y + (size_t)row * DD + nb * 128 + wn * 32;
        float* y1 = y0 + 8 * DD;
        #pragma unroll
        for (int fn = 0; fn < 4; ++fn) {
            int cc = fn * 8 + c2;
            *(float2*)(y0 + cc) = make_float2(d[fm][fn][0], d[fm][fn][1]);
            *(float2*)(y1 + cc) = make_float2(d[fm][fn][2], d[fm][fn][3]);
        }
    }
}

// ---------------- K5: gcn gate + residual add (in place on Yin/Yout) ----------------
__global__ void gcn_gate_kernel(const float* __restrict__ x_ext, int use_mid,
                                const float* __restrict__ Wgi, const float* __restrict__ bgi_p,
                                const float* __restrict__ Wgo, const float* __restrict__ bgo_p) {
    const float* x = use_mid ? g_xmid : x_ext;
    int warp = (blockIdx.x * blockDim.x + threadIdx.x) >> 5;
    int lane = threadIdx.x & 31;
    if (warp >= Bq * NN) return;
    size_t base = (size_t)warp * DD;
    float si = 0.f, so = 0.f;
    #pragma unroll
    for (int d = lane; d < DD; d += 32) {
        si += g_Yin [base + d] * Wgi[d];
        so += g_Yout[base + d] * Wgo[d];
    }
    #pragma unroll
    for (int off = 16; off; off >>= 1) {
        si += __shfl_xor_sync(0xffffffffu, si, off);
        so += __shfl_xor_sync(0xffffffffu, so, off);
    }
    float gi = 1.f / (1.f + expf(-si));
    float go = 1.f / (1.f + expf(-so));
    float bgi = bgi_p[0], bgo = bgo_p[0];
    #pragma unroll
    for (int d = lane; d < DD; d += 32) {
        float xv = x[base + d];
        g_Yin [base + d] = g_Yin [base + d] * gi + bgi + xv;
        g_Yout[base + d] = g_Yout[base + d] * go + bgo + xv;
    }
}

// ---------------- K6: fc GEMM  h[:, sel*H+c] = S @ W^T + 2b  (tf32, split-A) ----------------
#define FC_SMEM (3 * TILE_F * 4)   // 55296 bytes

__global__ void __launch_bounds__(256, 2)
fc_mma_kernel(const float* __restrict__ Wi, const float* __restrict__ bi,
              const float* __restrict__ Wo, const float* __restrict__ bo) {
    extern __shared__ float dynf[];   // Ahi | Alo | Bs
    const int tid  = threadIdx.x;
    const int lane = tid & 31, warp = tid >> 5;
    const int wm = warp & 1, wn = warp >> 1;
    const int sel = blockIdx.y;
    const int m0  = blockIdx.x * 128;

    const float* S    = sel ? g_Yout : g_Yin;
    const float* W    = sel ? Wo : Wi;
    const float* bias = sel ? bo : bi;

    float* Ahi = dynf;
    float* Alo = dynf + TILE_F;
    float* Bs  = dynf + 2 * TILE_F;
    const int r = lane >> 2, c = lane & 3;

    float d[4][4][4] = {};

    for (int kt = 0; kt < DD / 32; ++kt) {
        int k0 = kt * 32;
        __syncthreads();
        #pragma unroll
        for (int u = 0; u < 4; ++u) {
            int e = tid + 256 * u; int row = e >> 3; int kq = (e & 7) << 2;
            float4 v = *(const float4*)(S + (size_t)(m0 + row) * DD + k0 + kq);
            float4 h, lo;
            h.x = tf32r(v.x); lo.x = tf32r(v.x - h.x);
            h.y = tf32r(v.y); lo.y = tf32r(v.y - h.y);
            h.z = tf32r(v.z); lo.z = tf32r(v.z - h.z);
            h.w = tf32r(v.w); lo.w = tf32r(v.w - h.w);
            *(float4*)(Ahi + row * TSTRIDE + kq) = h;
            *(float4*)(Alo + row * TSTRIDE + kq) = lo;
            float4 w = *(const float4*)(W + (size_t)row * DD + k0 + kq);
            w.x = tf32r(w.x); w.y = tf32r(w.y); w.z = tf32r(w.z); w.w = tf32r(w.w);
            *(float4*)(Bs + row * TSTRIDE + kq) = w;
        }
        __syncthreads();

        #pragma unroll
        for (int kk = 0; kk < 32; kk += 8) {
            uint32_t bf[4][2];
            #pragma unroll
            for (int fn = 0; fn < 4; ++fn) {
                int n = wn * 32 + fn * 8 + r;
                bf[fn][0] = __float_as_uint(Bs[n * TSTRIDE + kk + c]);
                bf[fn][1] = __float_as_uint(Bs[n * TSTRIDE + kk + c + 4]);
            }
            #pragma unroll
            for (int sp = 0; sp < 2; ++sp) {
                const float* Asrc = sp ? Alo : Ahi;
                uint32_t a[4][4];
                #pragma unroll
                for (int fm = 0; fm < 4; ++fm) {
                    int m = wm * 64 + fm * 16 + r;
                    a[fm][0] = __float_as_uint(Asrc[m * TSTRIDE + kk + c]);
                    a[fm][1] = __float_as_uint(Asrc[(m + 8) * TSTRIDE + kk + c]);
                    a[fm][2] = __float_as_uint(Asrc[m * TSTRIDE + kk + c + 4]);
                    a[fm][3] = __float_as_uint(Asrc[(m + 8) * TSTRIDE + kk + c + 4]);
                }
                #pragma unroll
                for (int fm = 0; fm < 4; ++fm)
                    #pragma unroll
                    for (int fn = 0; fn < 4; ++fn)
                        MMA4(d[fm][fn], a[fm], bf[fn]);
            }
        }
    }

    const int c2 = (lane & 3) * 2;
    #pragma unroll
    for (int fm = 0; fm < 4; ++fm) {
        int row = m0 + wm * 64 + fm * 16 + r;
        #pragma unroll
        for (int fn = 0; fn < 4; ++fn) {
            int col = wn * 32 + fn * 8 + c2;
            float b0 = 2.f * bias[col], b1 = 2.f * bias[col + 1];
            float* h0 = g_h + (size_t)row * DD + sel * HH + col;
            float* h1 = g_h + (size_t)(row + 8) * DD + sel * HH + col;
            h0[0] = d[fm][fn][0] + b0;  h0[1] = d[fm][fn][1] + b1;
            h1[0] = d[fm][fn][2] + b0;  h1[1] = d[fm][fn][3] + b1;
        }
    }
}

// ---------------- K7: LayerNorm(2H) + exact GELU ----------------
__global__ void ln_gelu_kernel(const float* __restrict__ gw, const float* __restrict__ bw,
                               float* __restrict__ out_ext, int to_mid) {
    float* out = to_mid ? g_xmid : out_ext;
    int node = blockIdx.x;
    int t = threadIdx.x;
    float v = g_h[(size_t)node * DD + t];

    float s = v, s2 = v * v;
    #pragma unroll
    for (int off = 16; off; off >>= 1) {
        s  += __shfl_xor_sync(0xffffffffu, s,  off);
        s2 += __shfl_xor_sync(0xffffffffu, s2, off);
    }
    __shared__ float red[2][8];
    int w = t >> 5, lane = t & 31;
    if (lane == 0) { red[0][w] = s; red[1][w] = s2; }
    __syncthreads();
    s = 0.f; s2 = 0.f;
    #pragma unroll
    for (int i = 0; i < 8; i++) { s += red[0][i]; s2 += red[1][i]; }

    float mu  = s  * (1.f / DD);
    float var = s2 * (1.f / DD) - mu * mu;
    float rr  = rsqrtf(var + 1e-5f);
    float hn  = (v - mu) * rr * gw[t] + bw[t];
    out[(size_t)node * DD + t] = 0.5f * hn * (1.f + erff(hn * 0.70710678118654752f));
}

// ---------------- host launcher ----------------
extern "C" void kernel_launch(void* const* d_in, const int* in_sizes, int n_in,
                              void* d_out, int out_size) {
    (void)in_sizes; (void)n_in; (void)out_size;
    const float* x0  = (const float*)d_in[0];
    const float* lat = (const float*)d_in[1];
    const float* dep = (const float*)d_in[2];
    const float* rg  = (const float*)d_in[3];
    const float* Wgi = (const float*)d_in[4];
    const float* bgi = (const float*)d_in[5];
    const float* Wgo = (const float*)d_in[6];
    const float* bgo = (const float*)d_in[7];
    const float* Wi  = (const float*)d_in[8];
    const float* bi  = (const float*)d_in[9];
    const float* Wo  = (const float*)d_in[10];
    const float* bo  = (const float*)d_in[11];
    const float* lng = (const float*)d_in[12];
    const float* lnb = (const float*)d_in[13];
    float* out = (float*)d_out;

    cudaFuncSetAttribute(adj_mma_kernel, cudaFuncAttributeMaxDynamicSharedMemorySize, ADJ_SMEM);
    cudaFuncSetAttribute(fc_mma_kernel,  cudaFuncAttributeMaxDynamicSharedMemorySize, FC_SMEM);

    const int nodeWarpBlocks = (Bq * NN * 32) / 256;   // 2048

    for (int l = 0; l < LL; l++) {
        int use_mid = (l != 0);
        int to_mid  = (l != LL - 1);

        gate_kernel<<<nodeWarpBlocks, 256>>>(x0, use_mid, rg + l * DD);

        dim3 gB(NN / 32, NN / 32, Bq);
        buildA2_kernel<<<gB, dim3(32, 8)>>>(dep, lat);

        dim3 gX(DD / 32, NN / 32, Bq);
        xt_kernel<<<gX, dim3(32, 8)>>>(x0, use_mid);

        dim3 gM(DD / 128, NN / 128, Bq * 2);
        adj_mma_kernel<<<gM, 256, ADJ_SMEM>>>();

        gcn_gate_kernel<<<nodeWarpBlocks, 256>>>(x0, use_mid,
                                                 Wgi + l * DD, bgi + l,
                                                 Wgo + l * DD, bgo + l);

        dim3 gFc((Bq * NN) / 128, 2);
        fc_mma_kernel<<<gFc, 256, FC_SMEM>>>(Wi + (size_t)l * HH * DD, bi + l * HH,
                                             Wo + (size_t)l * HH * DD, bo + l * HH);

        ln_gelu_kernel<<<Bq * NN, 256>>>(lng + l * 2 * HH, lnb + l * 2 * HH,
                                         out, to_mid);
    }
}

// round 6
// speedup vs baseline: 2.8799x; 1.1345x over previous
#include <cuda_runtime.h>
#include <math.h>
#include <stdint.h>

#define Bq 16
#define NN 1024
#define DD 256
#define HH 128
#define LL 2

// ---------------- scratch (device globals; no allocation) ----------------
__device__ __align__(128) float g_gate[Bq * NN];
__device__ __align__(128) float g_Xt  [Bq * DD * NN];   // x^T [b,d,k] (tf32-rounded)
__device__ __align__(128) float g_Yin [Bq * NN * DD];
__device__ __align__(128) float g_Yout[Bq * NN * DD];
__device__ __align__(128) float g_xmid[Bq * NN * DD];
__device__ __align__(128) float g_h   [Bq * NN * DD];   // 2H == D

// ---------------- helpers ----------------
__device__ __forceinline__ uint32_t smem_u32(const void* p) {
    uint32_t a;
    asm("{ .reg .u64 t; cvta.to.shared.u64 t, %1; cvt.u32.u64 %0, t; }" : "=r"(a) : "l"(p));
    return a;
}
__device__ __forceinline__ float tf32r(float x) {
    uint32_t r;
    asm("cvt.rna.tf32.f32 %0, %1;" : "=r"(r) : "f"(x));
    return __uint_as_float(r);
}
__device__ __forceinline__ void cp16(uint32_t dst, const float* src) {
    asm volatile("cp.async.cg.shared.global [%0], [%1], 16;" :: "r"(dst), "l"(src) : "memory");
}
#define CP_COMMIT() asm volatile("cp.async.commit_group;" ::: "memory")
#define CP_WAIT0()  asm volatile("cp.async.wait_group 0;" ::: "memory")

#define MMA4(D, A, B) \
    asm volatile("mma.sync.aligned.m16n8k8.row.col.f32.tf32.tf32.f32 " \
        "{%0,%1,%2,%3}, {%4,%5,%6,%7}, {%8,%9}, {%0,%1,%2,%3};" \
        : "+f"((D)[0]), "+f"((D)[1]), "+f"((D)[2]), "+f"((D)[3]) \
        : "r"((A)[0]), "r"((A)[1]), "r"((A)[2]), "r"((A)[3]), \
          "r"((B)[0]), "r"((B)[1]))

// smem geometry
#define TSTRIDE 36
#define B_TILE_F (256 * TSTRIDE)          // 9216 floats per B stage
#define A_TILE_F (128 * TSTRIDE)          // 4608 floats per A stage (SEL1 uses 32*132=4224)
#define ADJ_SMEM ((2 * B_TILE_F + 2 * A_TILE_F) * 4)   // 110592 bytes
#define FC_TILE_F (128 * TSTRIDE)
#define FC_SMEM (3 * FC_TILE_F * 4)       // 55296 bytes

// ---------------- K1: per-node refine gate ----------------
__global__ void gate_kernel(const float* __restrict__ x_ext, int use_mid,
                            const float* __restrict__ rg) {
    const float* x = use_mid ? g_xmid : x_ext;
    int warp = (blockIdx.x * blockDim.x + threadIdx.x) >> 5;
    int lane = threadIdx.x & 31;
    if (warp >= Bq * NN) return;
    const float* xp = x + (size_t)warp * DD;
    float s = 0.f;
    #pragma unroll
    for (int d = lane; d < DD; d += 32) s += xp[d] * rg[d];
    #pragma unroll
    for (int off = 16; off; off >>= 1) s += __shfl_xor_sync(0xffffffffu, s, off);
    if (lane == 0) g_gate[warp] = 1.f / (1.f + expf(-s));
}

// ---------------- K2: transpose x -> Xt [b,d,k], tf32-rounded ----------------
__global__ void xt_kernel(const float* __restrict__ x_ext, int use_mid) {
    __shared__ float s[32][33];
    const float* x = use_mid ? g_xmid : x_ext;
    int b  = blockIdx.z;
    int k0 = blockIdx.y * 32;
    int d0 = blockIdx.x * 32;
    int tx = threadIdx.x, ty = threadIdx.y;
    const float* xb = x + (size_t)b * NN * DD;
    float* xtb = g_Xt + (size_t)b * DD * NN;
    #pragma unroll
    for (int u = 0; u < 4; ++u)
        s[ty + 8 * u][tx] = xb[(size_t)(k0 + ty + 8 * u) * DD + d0 + tx];
    __syncthreads();
    #pragma unroll
    for (int u = 0; u < 4; ++u)
        xtb[(size_t)(d0 + ty + 8 * u) * NN + k0 + tx] = tf32r(s[tx][ty + 8 * u]);
}

// ---------------- K3: fused adjacency-blend + tf32 GEMM + gcn-gate + residual ----------------
// CTA: 128 rows x 256 cols (full feature width), K=1024 in steps of 32. 512 threads.
// SEL0: A_in[i,j]  = g[i]*dep[i,j] + (1-g[i])*lat[i,j]   (m-major smem, stride 36)
// SEL1: A_out[j,i] = g[j]*dep[i,j] + (1-g[j])*lat[i,j]   (k-major smem, stride 132)
extern __shared__ float dynf[];

template <int SEL>
__device__ __forceinline__ void adj_mainloop(
    const float* __restrict__ dep, const float* __restrict__ lat,
    const float* __restrict__ Xt, const float* __restrict__ gvec,
    int m0, int tid, float d[4][4][4])
{
    const int lane = tid & 31;
    const int warp = tid >> 5;
    const int wm = warp & 1, wn = warp >> 1;
    const int r = lane >> 2, c = lane & 3;
    const uint32_t sb = smem_u32(dynf);

    // producer coords (fixed across K iterations)
    int arow0 = 0, arow1 = 0, acolq = 0, ai0 = 0, ai1 = 0, aj4 = 0;
    float gi0 = 0.f, gi1 = 0.f;
    float4 gj = make_float4(0.f, 0.f, 0.f, 0.f);
    if (SEL == 0) {
        arow0 = tid >> 3; arow1 = arow0 + 64; acolq = tid & 7;
        gi0 = gvec[m0 + arow0]; gi1 = gvec[m0 + arow1];
    } else {
        ai0 = tid >> 5; ai1 = ai0 + 16; aj4 = (tid & 31) * 4;
        gj = *(const float4*)(gvec + m0 + aj4);
    }

    float4 dv0, dv1, lv0, lv1;

    auto loadA = [&](int k0) {
        if (SEL == 0) {
            dv0 = *(const float4*)(dep + (size_t)(m0 + arow0) * NN + k0 + acolq * 4);
            dv1 = *(const float4*)(dep + (size_t)(m0 + arow1) * NN + k0 + acolq * 4);
            lv0 = *(const float4*)(lat + (size_t)(m0 + arow0) * NN + k0 + acolq * 4);
            lv1 = *(const float4*)(lat + (size_t)(m0 + arow1) * NN + k0 + acolq * 4);
        } else {
            dv0 = *(const float4*)(dep + (size_t)(k0 + ai0) * NN + m0 + aj4);
            dv1 = *(const float4*)(dep + (size_t)(k0 + ai1) * NN + m0 + aj4);
            lv0 = *(const float4*)(lat + (size_t)(k0 + ai0) * NN + m0 + aj4);
            lv1 = *(const float4*)(lat + (size_t)(k0 + ai1) * NN + m0 + aj4);
        }
    };
    auto storeA = [&](int stage) {
        float* As = dynf + 2 * B_TILE_F + stage * A_TILE_F;
        float4 o0, o1;
        if (SEL == 0) {
            o0.x = tf32r(fmaf(gi0, dv0.x - lv0.x, lv0.x));
            o0.y = tf32r(fmaf(gi0, dv0.y - lv0.y, lv0.y));
            o0.z = tf32r(fmaf(gi0, dv0.z - lv0.z, lv0.z));
            o0.w = tf32r(fmaf(gi0, dv0.w - lv0.w, lv0.w));
            o1.x = tf32r(fmaf(gi1, dv1.x - lv1.x, lv1.x));
            o1.y = tf32r(fmaf(gi1, dv1.y - lv1.y, lv1.y));
            o1.z = tf32r(fmaf(gi1, dv1.z - lv1.z, lv1.z));
            o1.w = tf32r(fmaf(gi1, dv1.w - lv1.w, lv1.w));
            *(float4*)(As + arow0 * TSTRIDE + acolq * 4) = o0;
            *(float4*)(As + arow1 * TSTRIDE + acolq * 4) = o1;
        } else {
            o0.x = tf32r(fmaf(gj.x, dv0.x - lv0.x, lv0.x));
            o0.y = tf32r(fmaf(gj.y, dv0.y - lv0.y, lv0.y));
            o0.z = tf32r(fmaf(gj.z, dv0.z - lv0.z, lv0.z));
            o0.w = tf32r(fmaf(gj.w, dv0.w - lv0.w, lv0.w));
            o1.x = tf32r(fmaf(gj.x, dv1.x - lv1.x, lv1.x));
            o1.y = tf32r(fmaf(gj.y, dv1.y - lv1.y, lv1.y));
            o1.z = tf32r(fmaf(gj.z, dv1.z - lv1.z, lv1.z));
            o1.w = tf32r(fmaf(gj.w, dv1.w - lv1.w, lv1.w));
            *(float4*)(As + ai0 * 132 + aj4) = o0;
            *(float4*)(As + ai1 * 132 + aj4) = o1;
        }
    };
    auto loadB = [&](int k0, int stage) {
        uint32_t dstb = sb + (uint32_t)(stage * B_TILE_F) * 4;
        #pragma unroll
        for (int u = 0; u < 4; ++u) {
            int e = tid + 512 * u; int row = e >> 3; int colq = e & 7;
            cp16(dstb + (uint32_t)(row * TSTRIDE + colq * 4) * 4,
                 Xt + (size_t)row * NN + k0 + colq * 4);
        }
    };

    // prologue
    loadA(0); loadB(0, 0); CP_COMMIT();
    storeA(0);
    CP_WAIT0(); __syncthreads();

    const int KT = NN / 32;
    for (int kt = 0; kt < KT; ++kt) {
        int cur = kt & 1, nxt = cur ^ 1;
        bool more = (kt + 1) < KT;
        if (more) { loadA((kt + 1) * 32); loadB((kt + 1) * 32, nxt); CP_COMMIT(); }

        const float* As = dynf + 2 * B_TILE_F + cur * A_TILE_F;
        const float* Bs = dynf + cur * B_TILE_F;
        #pragma unroll
        for (int kk = 0; kk < 32; kk += 8) {
            uint32_t a[4][4], bf[4][2];
            #pragma unroll
            for (int fm = 0; fm < 4; ++fm) {
                int m = wm * 64 + fm * 16 + r;
                if (SEL == 0) {
                    a[fm][0] = __float_as_uint(As[m * TSTRIDE + kk + c]);
                    a[fm][1] = __float_as_uint(As[(m + 8) * TSTRIDE + kk + c]);
                    a[fm][2] = __float_as_uint(As[m * TSTRIDE + kk + c + 4]);
                    a[fm][3] = __float_as_uint(As[(m + 8) * TSTRIDE + kk + c + 4]);
                } else {
                    a[fm][0] = __float_as_uint(As[(kk + c) * 132 + m]);
                    a[fm][1] = __float_as_uint(As[(kk + c) * 132 + m + 8]);
                    a[fm][2] = __float_as_uint(As[(kk + c + 4) * 132 + m]);
                    a[fm][3] = __float_as_uint(As[(kk + c + 4) * 132 + m + 8]);
                }
            }
            #pragma unroll
            for (int fn = 0; fn < 4; ++fn) {
                int n = wn * 32 + fn * 8 + r;
                bf[fn][0] = __float_as_uint(Bs[n * TSTRIDE + kk + c]);
                bf[fn][1] = __float_as_uint(Bs[n * TSTRIDE + kk + c + 4]);
            }
            #pragma unroll
            for (int fm = 0; fm < 4; ++fm)
                #pragma unroll
                for (int fn = 0; fn < 4; ++fn)
                    MMA4(d[fm][fn], a[fm], bf[fn]);
        }
        if (more) { storeA(nxt); CP_WAIT0(); }
        __syncthreads();
    }
}

__global__ void __launch_bounds__(512, 1)
adj_fused_kernel(const float* __restrict__ dep, const float* __restrict__ lat,
                 const float* __restrict__ x_ext, int use_mid,
                 const float* __restrict__ Wgi, const float* __restrict__ bgi,
                 const float* __restrict__ Wgo, const float* __restrict__ bgo) {
    __shared__ float sgate[128];
    const int tid = threadIdx.x;
    const int m0  = blockIdx.x * 128;
    const int b   = blockIdx.y;
    const int sel = blockIdx.z;

    if (tid < 128) sgate[tid] = 0.f;

    const float* dep_b = dep + (size_t)b * NN * NN;
    const float* lat_b = lat + (size_t)b * NN * NN;
    const float* Xt_b  = g_Xt + (size_t)b * DD * NN;
    const float* gvec  = g_gate + b * NN;

    float d[4][4][4] = {};
    if (sel == 0) adj_mainloop<0>(dep_b, lat_b, Xt_b, gvec, m0, tid, d);
    else          adj_mainloop<1>(dep_b, lat_b, Xt_b, gvec, m0, tid, d);

    const float* Wg = sel ? Wgo : Wgi;
    const float  bgs = sel ? bgo[0] : bgi[0];
    float* Y = (sel ? g_Yout : g_Yin) + (size_t)b * NN * DD;
    const float* xres = (use_mid ? g_xmid : x_ext) + (size_t)b * NN * DD;

    const int lane = tid & 31, warp = tid >> 5;
    const int wm = warp & 1, wn = warp >> 1;
    const int r = lane >> 2, c2 = (lane & 3) * 2;

    // ---- gate logit: partial dot over this thread's columns ----
    float p0[4], p1[4];
    #pragma unroll
    for (int fm = 0; fm < 4; ++fm) {
        p0[fm] = 0.f; p1[fm] = 0.f;
        #pragma unroll
        for (int fn = 0; fn < 4; ++fn) {
            int col = wn * 32 + fn * 8 + c2;
            float w0 = Wg[col], w1 = Wg[col + 1];
            p0[fm] += d[fm][fn][0] * w0 + d[fm][fn][1] * w1;
            p1[fm] += d[fm][fn][2] * w0 + d[fm][fn][3] * w1;
        }
    }
    #pragma unroll
    for (int off = 1; off <= 2; off <<= 1) {
        #pragma unroll
        for (int fm = 0; fm < 4; ++fm) {
            p0[fm] += __shfl_xor_sync(0xffffffffu, p0[fm], off);
            p1[fm] += __shfl_xor_sync(0xffffffffu, p1[fm], off);
        }
    }
    if ((lane & 3) == 0) {
        #pragma unroll
        for (int fm = 0; fm < 4; ++fm) {
            atomicAdd(&sgate[wm * 64 + fm * 16 + r],     p0[fm]);
            atomicAdd(&sgate[wm * 64 + fm * 16 + r + 8], p1[fm]);
        }
    }
    __syncthreads();

    // ---- write Y = Ax*gate + bg + x ----
    #pragma unroll
    for (int fm = 0; fm < 4; ++fm) {
        int lr = wm * 64 + fm * 16 + r;
        float ga = 1.f / (1.f + expf(-sgate[lr]));
        float gb2 = 1.f / (1.f + expf(-sgate[lr + 8]));
        const float* x0p = xres + (size_t)(m0 + lr) * DD;
        const float* x1p = x0p + 8 * DD;
        float* y0p = Y + (size_t)(m0 + lr) * DD;
        float* y1p = y0p + 8 * DD;
        #pragma unroll
        for (int fn = 0; fn < 4; ++fn) {
            int col = wn * 32 + fn * 8 + c2;
            float2 xv0 = *(const float2*)(x0p + col);
            float2 xv1 = *(const float2*)(x1p + col);
            float2 o0, o1;
            o0.x = d[fm][fn][0] * ga + bgs + xv0.x;
            o0.y = d[fm][fn][1] * ga + bgs + xv0.y;
            o1.x = d[fm][fn][2] * gb2 + bgs + xv1.x;
            o1.y = d[fm][fn][3] * gb2 + bgs + xv1.y;
            *(float2*)(y0p + col) = o0;
            *(float2*)(y1p + col) = o1;
        }
    }
}

// ---------------- K4: fc GEMM  h[:, sel*H+c] = S @ W^T + 2b  (tf32, split-A) ----------------
__global__ void __launch_bounds__(256, 2)
fc_mma_kernel(const float* __restrict__ Wi, const float* __restrict__ bi,
              const float* __restrict__ Wo, const float* __restrict__ bo) {
    const int tid  = threadIdx.x;
    const int lane = tid & 31, warp = tid >> 5;
    const int wm = warp & 1, wn = warp >> 1;
    const int sel = blockIdx.y;
    const int m0  = blockIdx.x * 128;

    const float* S    = sel ? g_Yout : g_Yin;
    const float* W    = sel ? Wo : Wi;
    const float* bias = sel ? bo : bi;

    float* Ahi = dynf;
    float* Alo = dynf + FC_TILE_F;
    float* Bs  = dynf + 2 * FC_TILE_F;
    const int r = lane >> 2, c = lane & 3;

    float d[4][4][4] = {};

    for (int kt = 0; kt < DD / 32; ++kt) {
        int k0 = kt * 32;
        __syncthreads();
        #pragma unroll
        for (int u = 0; u < 4; ++u) {
            int e = tid + 256 * u; int row = e >> 3; int kq = (e & 7) << 2;
            float4 v = *(const float4*)(S + (size_t)(m0 + row) * DD + k0 + kq);
            float4 h, lo;
            h.x = tf32r(v.x); lo.x = tf32r(v.x - h.x);
            h.y = tf32r(v.y); lo.y = tf32r(v.y - h.y);
            h.z = tf32r(v.z); lo.z = tf32r(v.z - h.z);
            h.w = tf32r(v.w); lo.w = tf32r(v.w - h.w);
            *(float4*)(Ahi + row * TSTRIDE + kq) = h;
            *(float4*)(Alo + row * TSTRIDE + kq) = lo;
            float4 w = *(const float4*)(W + (size_t)row * DD + k0 + kq);
            w.x = tf32r(w.x); w.y = tf32r(w.y); w.z = tf32r(w.z); w.w = tf32r(w.w);
            *(float4*)(Bs + row * TSTRIDE + kq) = w;
        }
        __syncthreads();

        #pragma unroll
        for (int kk = 0; kk < 32; kk += 8) {
            uint32_t bf[4][2];
            #pragma unroll
            for (int fn = 0; fn < 4; ++fn) {
                int n = wn * 32 + fn * 8 + r;
                bf[fn][0] = __float_as_uint(Bs[n * TSTRIDE + kk + c]);
                bf[fn][1] = __float_as_uint(Bs[n * TSTRIDE + kk + c + 4]);
            }
            #pragma unroll
            for (int sp = 0; sp < 2; ++sp) {
                const float* Asrc = sp ? Alo : Ahi;
                uint32_t a[4][4];
                #pragma unroll
                for (int fm = 0; fm < 4; ++fm) {
                    int m = wm * 64 + fm * 16 + r;
                    a[fm][0] = __float_as_uint(Asrc[m * TSTRIDE + kk + c]);
                    a[fm][1] = __float_as_uint(Asrc[(m + 8) * TSTRIDE + kk + c]);
                    a[fm][2] = __float_as_uint(Asrc[m * TSTRIDE + kk + c + 4]);
                    a[fm][3] = __float_as_uint(Asrc[(m + 8) * TSTRIDE + kk + c + 4]);
                }
                #pragma unroll
                for (int fm = 0; fm < 4; ++fm)
                    #pragma unroll
                    for (int fn = 0; fn < 4; ++fn)
                        MMA4(d[fm][fn], a[fm], bf[fn]);
            }
        }
    }

    const int c2 = (lane & 3) * 2;
    #pragma unroll
    for (int fm = 0; fm < 4; ++fm) {
        int row = m0 + wm * 64 + fm * 16 + r;
        #pragma unroll
        for (int fn = 0; fn < 4; ++fn) {
            int col = wn * 32 + fn * 8 + c2;
            float b0 = 2.f * bias[col], b1 = 2.f * bias[col + 1];
            float* h0 = g_h + (size_t)row * DD + sel * HH + col;
            float* h1 = g_h + (size_t)(row + 8) * DD + sel * HH + col;
            h0[0] = d[fm][fn][0] + b0;  h0[1] = d[fm][fn][1] + b1;
            h1[0] = d[fm][fn][2] + b0;  h1[1] = d[fm][fn][3] + b1;
        }
    }
}

// ---------------- K5: LayerNorm(2H) + exact GELU ----------------
__global__ void ln_gelu_kernel(const float* __restrict__ gw, const float* __restrict__ bw,
                               float* __restrict__ out_ext, int to_mid) {
    float* out = to_mid ? g_xmid : out_ext;
    int node = blockIdx.x;
    int t = threadIdx.x;
    float v = g_h[(size_t)node * DD + t];

    float s = v, s2 = v * v;
    #pragma unroll
    for (int off = 16; off; off >>= 1) {
        s  += __shfl_xor_sync(0xffffffffu, s,  off);
        s2 += __shfl_xor_sync(0xffffffffu, s2, off);
    }
    __shared__ float red[2][8];
    int w = t >> 5, lane = t & 31;
    if (lane == 0) { red[0][w] = s; red[1][w] = s2; }
    __syncthreads();
    s = 0.f; s2 = 0.f;
    #pragma unroll
    for (int i = 0; i < 8; i++) { s += red[0][i]; s2 += red[1][i]; }

    float mu  = s  * (1.f / DD);
    float var = s2 * (1.f / DD) - mu * mu;
    float rr  = rsqrtf(var + 1e-5f);
    float hn  = (v - mu) * rr * gw[t] + bw[t];
    out[(size_t)node * DD + t] = 0.5f * hn * (1.f + erff(hn * 0.70710678118654752f));
}

// ---------------- host launcher ----------------
extern "C" void kernel_launch(void* const* d_in, const int* in_sizes, int n_in,
                              void* d_out, int out_size) {
    (void)in_sizes; (void)n_in; (void)out_size;
    const float* x0  = (const float*)d_in[0];
    const float* lat = (const float*)d_in[1];
    const float* dep = (const float*)d_in[2];
    const float* rg  = (const float*)d_in[3];
    const float* Wgi = (const float*)d_in[4];
    const float* bgi = (const float*)d_in[5];
    const float* Wgo = (const float*)d_in[6];
    const float* bgo = (const float*)d_in[7];
    const float* Wi  = (const float*)d_in[8];
    const float* bi  = (const float*)d_in[9];
    const float* Wo  = (const float*)d_in[10];
    const float* bo  = (const float*)d_in[11];
    const float* lng = (const float*)d_in[12];
    const float* lnb = (const float*)d_in[13];
    float* out = (float*)d_out;

    cudaFuncSetAttribute(adj_fused_kernel, cudaFuncAttributeMaxDynamicSharedMemorySize, ADJ_SMEM);
    cudaFuncSetAttribute(fc_mma_kernel,    cudaFuncAttributeMaxDynamicSharedMemorySize, FC_SMEM);

    const int nodeWarpBlocks = (Bq * NN * 32) / 256;   // 2048

    for (int l = 0; l < LL; l++) {
        int use_mid = (l != 0);
        int to_mid  = (l != LL - 1);

        gate_kernel<<<nodeWarpBlocks, 256>>>(x0, use_mid, rg + l * DD);

        dim3 gX(DD / 32, NN / 32, Bq);
        xt_kernel<<<gX, dim3(32, 8)>>>(x0, use_mid);

        dim3 gM(NN / 128, Bq, 2);
        adj_fused_kernel<<<gM, 512, ADJ_SMEM>>>(dep, lat, x0, use_mid,
                                                Wgi + l * DD, bgi + l,
                                                Wgo + l * DD, bgo + l);

        dim3 gFc((Bq * NN) / 128, 2);
        fc_mma_kernel<<<gFc, 256, FC_SMEM>>>(Wi + (size_t)l * HH * DD, bi + l * HH,
                                             Wo + (size_t)l * HH * DD, bo + l * HH);

        ln_gelu_kernel<<<Bq * NN, 256>>>(lng + l * 2 * HH, lnb + l * 2 * HH,
                                         out, to_mid);
    }
}

// round 10
// speedup vs baseline: 3.9620x; 1.3758x over previous
#include <cuda_runtime.h>
#include <cuda_fp16.h>
#include <math.h>
#include <stdint.h>

#define Bq 16
#define NN 1024
#define DD 256
#define HH 128
#define LL 2

// ---------------- scratch (device globals; no allocation) ----------------
__device__ __align__(128) float  g_gate[Bq * NN];
__device__ __align__(128) __half g_Xt  [Bq * DD * NN];  // x^T [b,d,k] fp16
__device__ __align__(128) float  g_Yin [Bq * NN * DD];
__device__ __align__(128) float  g_Yout[Bq * NN * DD];
__device__ __align__(128) float  g_xmid[Bq * NN * DD];

// ---------------- helpers ----------------
__device__ __forceinline__ uint32_t smem_u32(const void* p) {
    uint32_t a;
    asm("{ .reg .u64 t; cvta.to.shared.u64 t, %1; cvt.u32.u64 %0, t; }" : "=r"(a) : "l"(p));
    return a;
}
__device__ __forceinline__ void cp16(uint32_t dst, const void* src) {
    asm volatile("cp.async.cg.shared.global [%0], [%1], 16;" :: "r"(dst), "l"(src) : "memory");
}
#define CP_COMMIT() asm volatile("cp.async.commit_group;" ::: "memory")
#define CP_WAIT0()  asm volatile("cp.async.wait_group 0;" ::: "memory")

#define MMAH(D, A, B) \
    asm volatile("mma.sync.aligned.m16n8k16.row.col.f32.f16.f16.f32 " \
        "{%0,%1,%2,%3}, {%4,%5,%6,%7}, {%8,%9}, {%0,%1,%2,%3};" \
        : "+f"((D)[0]), "+f"((D)[1]), "+f"((D)[2]), "+f"((D)[3]) \
        : "r"((A)[0]), "r"((A)[1]), "r"((A)[2]), "r"((A)[3]), \
          "r"((B)[0]), "r"((B)[1]))

// adjacency kernel smem geometry (halves)
#define BSTR 40
#define ASTR 40
#define MSTR 136                         // SEL1 k-major stride
#define B_TILE_H (256 * BSTR)            // 10240 halves
#define A_TILE_H (128 * ASTR)            // 5120 halves (>= 32*136)
#define ADJ_SMEM ((2 * B_TILE_H + 2 * A_TILE_H) * 2)   // 61440 bytes

// fc kernel smem
#define FC_AST 40
#define FC_TILE_H (128 * FC_AST)         // 5120 halves per tile
#define FC_SMEM (128 * 260 * 4)          // 133120 bytes (hbuf phase dominates)

extern __shared__ char smemc[];

// ---------------- K1: per-node refine gate ----------------
__global__ void gate_kernel(const float* __restrict__ x_ext, int use_mid,
                            const float* __restrict__ rg) {
    const float* x = use_mid ? g_xmid : x_ext;
    int warp = (blockIdx.x * blockDim.x + threadIdx.x) >> 5;
    int lane = threadIdx.x & 31;
    if (warp >= Bq * NN) return;
    const float* xp = x + (size_t)warp * DD;
    float s = 0.f;
    #pragma unroll
    for (int d = lane; d < DD; d += 32) s += xp[d] * rg[d];
    #pragma unroll
    for (int off = 16; off; off >>= 1) s += __shfl_xor_sync(0xffffffffu, s, off);
    if (lane == 0) g_gate[warp] = 1.f / (1.f + expf(-s));
}

// ---------------- K2: transpose x -> Xt [b,d,k], fp16 ----------------
__global__ void xt_kernel(const float* __restrict__ x_ext, int use_mid) {
    __shared__ float s[32][33];
    const float* x = use_mid ? g_xmid : x_ext;
    int b  = blockIdx.z;
    int k0 = blockIdx.y * 32;
    int d0 = blockIdx.x * 32;
    int tx = threadIdx.x, ty = threadIdx.y;
    const float* xb = x + (size_t)b * NN * DD;
    __half* xtb = g_Xt + (size_t)b * DD * NN;
    #pragma unroll
    for (int u = 0; u < 4; ++u)
        s[ty + 8 * u][tx] = xb[(size_t)(k0 + ty + 8 * u) * DD + d0 + tx];
    __syncthreads();
    #pragma unroll
    for (int u = 0; u < 4; ++u)
        xtb[(size_t)(d0 + ty + 8 * u) * NN + k0 + tx] = __float2half_rn(s[tx][ty + 8 * u]);
}

// ---------------- K3: fused adjacency-blend + fp16 GEMM + gcn-gate + residual ----------------
// CTA: 128 rows x 256 cols, K=1024 in steps of 32. 512 threads.
template <int SEL>
__device__ __forceinline__ void adj_mainloop(
    const float* __restrict__ dep, const float* __restrict__ lat,
    const __half* __restrict__ Xt, const float* __restrict__ gvec,
    int m0, int tid, float d[4][4][4])
{
    __half* sh = (__half*)smemc;            // B: [0, 2*B_TILE_H), A: [2*B_TILE_H, +2*A_TILE_H)
    const int lane = tid & 31;
    const int warp = tid >> 5;
    const int wm = warp & 1, wn = warp >> 1;
    const int g = lane >> 2, t4 = lane & 3;
    const uint32_t sb = smem_u32(sh);

    // producer coords
    int arow = 0, acolq = 0, ai = 0, aj8 = 0;
    float gi = 0.f;
    float gj8[8];
    if (SEL == 0) {
        arow = tid >> 2; acolq = tid & 3;
        gi = gvec[m0 + arow];
    } else {
        ai = tid >> 4; aj8 = (tid & 15) * 8;
        #pragma unroll
        for (int q = 0; q < 8; ++q) gj8[q] = gvec[m0 + aj8 + q];
    }

    float4 dv0, dv1, lv0, lv1;

    auto loadA = [&](int k0) {
        if (SEL == 0) {
            const float* dp = dep + (size_t)(m0 + arow) * NN + k0 + acolq * 8;
            const float* lp = lat + (size_t)(m0 + arow) * NN + k0 + acolq * 8;
            dv0 = *(const float4*)dp;  dv1 = *(const float4*)(dp + 4);
            lv0 = *(const float4*)lp;  lv1 = *(const float4*)(lp + 4);
        } else {
            const float* dp = dep + (size_t)(k0 + ai) * NN + m0 + aj8;
            const float* lp = lat + (size_t)(k0 + ai) * NN + m0 + aj8;
            dv0 = *(const float4*)dp;  dv1 = *(const float4*)(dp + 4);
            lv0 = *(const float4*)lp;  lv1 = *(const float4*)(lp + 4);
        }
    };
    auto storeA = [&](int stage) {
        __half* As = sh + 2 * B_TILE_H + stage * A_TILE_H;
        float v[8];
        if (SEL == 0) {
            v[0] = fmaf(gi, dv0.x - lv0.x, lv0.x); v[1] = fmaf(gi, dv0.y - lv0.y, lv0.y);
            v[2] = fmaf(gi, dv0.z - lv0.z, lv0.z); v[3] = fmaf(gi, dv0.w - lv0.w, lv0.w);
            v[4] = fmaf(gi, dv1.x - lv1.x, lv1.x); v[5] = fmaf(gi, dv1.y - lv1.y, lv1.y);
            v[6] = fmaf(gi, dv1.z - lv1.z, lv1.z); v[7] = fmaf(gi, dv1.w - lv1.w, lv1.w);
        } else {
            v[0] = fmaf(gj8[0], dv0.x - lv0.x, lv0.x); v[1] = fmaf(gj8[1], dv0.y - lv0.y, lv0.y);
            v[2] = fmaf(gj8[2], dv0.z - lv0.z, lv0.z); v[3] = fmaf(gj8[3], dv0.w - lv0.w, lv0.w);
            v[4] = fmaf(gj8[4], dv1.x - lv1.x, lv1.x); v[5] = fmaf(gj8[5], dv1.y - lv1.y, lv1.y);
            v[6] = fmaf(gj8[6], dv1.z - lv1.z, lv1.z); v[7] = fmaf(gj8[7], dv1.w - lv1.w, lv1.w);
        }
        __half2 h2[4];
        #pragma unroll
        for (int q = 0; q < 4; ++q) h2[q] = __floats2half2_rn(v[2 * q], v[2 * q + 1]);
        uint4 pk = *(const uint4*)h2;
        if (SEL == 0) *(uint4*)(As + arow * ASTR + acolq * 8) = pk;
        else          *(uint4*)(As + ai * MSTR + aj8) = pk;
    };
    auto loadB = [&](int k0, int stage) {
        uint32_t dstb = sb + (uint32_t)(stage * B_TILE_H) * 2;
        #pragma unroll
        for (int u = 0; u < 2; ++u) {
            int e = tid + 512 * u; int row = e >> 2; int colq = e & 3;
            cp16(dstb + (uint32_t)(row * BSTR + colq * 8) * 2,
                 Xt + (size_t)row * NN + k0 + colq * 8);
        }
    };

    // prologue
    loadA(0); loadB(0, 0); CP_COMMIT();
    storeA(0);
    CP_WAIT0(); __syncthreads();

    const int KT = NN / 32;
    for (int kt = 0; kt < KT; ++kt) {
        int cur = kt & 1, nxt = cur ^ 1;
        bool more = (kt + 1) < KT;
        if (more) { loadA((kt + 1) * 32); loadB((kt + 1) * 32, nxt); CP_COMMIT(); }

        const __half* As = sh + 2 * B_TILE_H + cur * A_TILE_H;
        const __half* Bs = sh + cur * B_TILE_H;
        #pragma unroll
        for (int kk = 0; kk < 32; kk += 16) {
            uint32_t a[4][4], bf[4][2];
            #pragma unroll
            for (int fm = 0; fm < 4; ++fm) {
                int m = wm * 64 + fm * 16 + g;
                if (SEL == 0) {
                    a[fm][0] = *(const uint32_t*)(As + m * ASTR + kk + 2 * t4);
                    a[fm][1] = *(const uint32_t*)(As + (m + 8) * ASTR + kk + 2 * t4);
                    a[fm][2] = *(const uint32_t*)(As + m * ASTR + kk + 2 * t4 + 8);
                    a[fm][3] = *(const uint32_t*)(As + (m + 8) * ASTR + kk + 2 * t4 + 8);
                } else {
                    const uint16_t* Au = (const uint16_t*)As;
                    uint32_t k0r = (kk + 2 * t4) * MSTR, k1r = k0r + MSTR;
                    uint32_t k8r = k0r + 8 * MSTR, k9r = k8r + MSTR;
                    a[fm][0] = (uint32_t)Au[k0r + m] | ((uint32_t)Au[k1r + m] << 16);
                    a[fm][1] = (uint32_t)Au[k0r + m + 8] | ((uint32_t)Au[k1r + m + 8] << 16);
                    a[fm][2] = (uint32_t)Au[k8r + m] | ((uint32_t)Au[k9r + m] << 16);
                    a[fm][3] = (uint32_t)Au[k8r + m + 8] | ((uint32_t)Au[k9r + m + 8] << 16);
                }
            }
            #pragma unroll
            for (int fn = 0; fn < 4; ++fn) {
                int n = wn * 32 + fn * 8 + g;
                bf[fn][0] = *(const uint32_t*)(Bs + n * BSTR + kk + 2 * t4);
                bf[fn][1] = *(const uint32_t*)(Bs + n * BSTR + kk + 2 * t4 + 8);
            }
            #pragma unroll
            for (int fm = 0; fm < 4; ++fm)
                #pragma unroll
                for (int fn = 0; fn < 4; ++fn)
                    MMAH(d[fm][fn], a[fm], bf[fn]);
        }
        if (more) { storeA(nxt); CP_WAIT0(); }
        __syncthreads();
    }
}

__global__ void __launch_bounds__(512, 1)
adj_fused_kernel(const float* __restrict__ dep, const float* __restrict__ lat,
                 const float* __restrict__ x_ext, int use_mid,
                 const float* __restrict__ Wgi, const float* __restrict__ bgi,
                 const float* __restrict__ Wgo, const float* __restrict__ bgo) {
    __shared__ float sgate[128];
    const int tid = threadIdx.x;
    const int m0  = blockIdx.x * 128;
    const int b   = blockIdx.y;
    const int sel = blockIdx.z;

    if (tid < 128) sgate[tid] = 0.f;

    const float* dep_b = dep + (size_t)b * NN * NN;
    const float* lat_b = lat + (size_t)b * NN * NN;
    const __half* Xt_b = g_Xt + (size_t)b * DD * NN;
    const float* gvec  = g_gate + b * NN;

    float d[4][4][4] = {};
    if (sel == 0) adj_mainloop<0>(dep_b, lat_b, Xt_b, gvec, m0, tid, d);
    else          adj_mainloop<1>(dep_b, lat_b, Xt_b, gvec, m0, tid, d);

    const float* Wg = sel ? Wgo : Wgi;
    const float  bgs = sel ? bgo[0] : bgi[0];
    float* Y = (sel ? g_Yout : g_Yin) + (size_t)b * NN * DD;
    const float* xres = (use_mid ? g_xmid : x_ext) + (size_t)b * NN * DD;

    const int lane = tid & 31, warp = tid >> 5;
    const int wm = warp & 1, wn = warp >> 1;
    const int g = lane >> 2, c2 = (lane & 3) * 2;

    // ---- gate logit ----
    float p0[4], p1[4];
    #pragma unroll
    for (int fm = 0; fm < 4; ++fm) {
        p0[fm] = 0.f; p1[fm] = 0.f;
        #pragma unroll
        for (int fn = 0; fn < 4; ++fn) {
            int col = wn * 32 + fn * 8 + c2;
            float w0 = Wg[col], w1 = Wg[col + 1];
            p0[fm] += d[fm][fn][0] * w0 + d[fm][fn][1] * w1;
            p1[fm] += d[fm][fn][2] * w0 + d[fm][fn][3] * w1;
        }
    }
    #pragma unroll
    for (int off = 1; off <= 2; off <<= 1) {
        #pragma unroll
        for (int fm = 0; fm < 4; ++fm) {
            p0[fm] += __shfl_xor_sync(0xffffffffu, p0[fm], off);
            p1[fm] += __shfl_xor_sync(0xffffffffu, p1[fm], off);
        }
    }
    if ((lane & 3) == 0) {
        #pragma unroll
        for (int fm = 0; fm < 4; ++fm) {
            atomicAdd(&sgate[wm * 64 + fm * 16 + g],     p0[fm]);
            atomicAdd(&sgate[wm * 64 + fm * 16 + g + 8], p1[fm]);
        }
    }
    __syncthreads();

    // ---- Y = Ax*gate + bg + x ----
    #pragma unroll
    for (int fm = 0; fm < 4; ++fm) {
        int lr = wm * 64 + fm * 16 + g;
        float ga  = 1.f / (1.f + expf(-sgate[lr]));
        float gb2 = 1.f / (1.f + expf(-sgate[lr + 8]));
        const float* x0p = xres + (size_t)(m0 + lr) * DD;
        const float* x1p = x0p + 8 * DD;
        float* y0p = Y + (size_t)(m0 + lr) * DD;
        float* y1p = y0p + 8 * DD;
        #pragma unroll
        for (int fn = 0; fn < 4; ++fn) {
            int col = wn * 32 + fn * 8 + c2;
            float2 xv0 = *(const float2*)(x0p + col);
            float2 xv1 = *(const float2*)(x1p + col);
            float2 o0, o1;
            o0.x = d[fm][fn][0] * ga + bgs + xv0.x;
            o0.y = d[fm][fn][1] * ga + bgs + xv0.y;
            o1.x = d[fm][fn][2] * gb2 + bgs + xv1.x;
            o1.y = d[fm][fn][3] * gb2 + bgs + xv1.y;
            *(float2*)(y0p + col) = o0;
            *(float2*)(y1p + col) = o1;
        }
    }
}

// ---------------- K4: fused fc GEMM (fp16 split-A) + LayerNorm + GELU ----------------
// CTA: 128 rows x full 256 h-cols (both sels). 512 threads, 16 warps.
// smem phase 1: Yhi/Ylo per sel (4 x FC_TILE_H) + W per sel (2 x FC_TILE_H) halves
// smem phase 2: hbuf float[128][260]
__global__ void __launch_bounds__(512, 1)
fc_ln_kernel(const float* __restrict__ Wi, const float* __restrict__ bi,
             const float* __restrict__ Wo, const float* __restrict__ bo,
             const float* __restrict__ gw, const float* __restrict__ bw,
             float* __restrict__ out_ext, int to_mid) {
    __half* sh   = (__half*)smemc;
    float*  hbuf = (float*)smemc;
    const int tid  = threadIdx.x;
    const int lane = tid & 31, warp = tid >> 5;
    const int wm = warp & 1, wq = warp >> 1;
    const int sel = wq >> 2, wn2 = wq & 3;
    const int g = lane >> 2, t4 = lane & 3;
    const int m0 = blockIdx.x * 128;

    // tile offsets in halves
    __half* sYh = sh;                              // [sel*2+hl] * FC_TILE_H
    __half* sW  = sh + 4 * FC_TILE_H;              // [sel] * FC_TILE_H

    float d[4][4][4] = {};

    for (int kt = 0; kt < DD / 32; ++kt) {
        int k0 = kt * 32;
        __syncthreads();
        #pragma unroll
        for (int u = 0; u < 4; ++u) {
            int e = tid + 512 * u;
            int ss = e >> 10; int rem = e & 1023;
            int row = rem >> 3, q = rem & 7;
            {   // Y -> hi/lo
                const float* S = ss ? g_Yout : g_Yin;
                float4 v = *(const float4*)(S + (size_t)(m0 + row) * DD + k0 + q * 4);
                float hx = __half2float(__float2half_rn(v.x));
                float hy = __half2float(__float2half_rn(v.y));
                float hz = __half2float(__float2half_rn(v.z));
                float hw = __half2float(__float2half_rn(v.w));
                __half2 hi0 = __floats2half2_rn(hx, hy), hi1 = __floats2half2_rn(hz, hw);
                __half2 lo0 = __floats2half2_rn(v.x - hx, v.y - hy);
                __half2 lo1 = __floats2half2_rn(v.z - hz, v.w - hw);
                __half* ph = sYh + (ss * 2 + 0) * FC_TILE_H + row * FC_AST + q * 4;
                __half* pl = sYh + (ss * 2 + 1) * FC_TILE_H + row * FC_AST + q * 4;
                *(__half2*)ph = hi0; *(__half2*)(ph + 2) = hi1;
                *(__half2*)pl = lo0; *(__half2*)(pl + 2) = lo1;
            }
            {   // W
                const float* Wp = ss ? Wo : Wi;
                float4 w = *(const float4*)(Wp + (size_t)row * DD + k0 + q * 4);
                __half* pw = sW + ss * FC_TILE_H + row * FC_AST + q * 4;
                *(__half2*)pw = __floats2half2_rn(w.x, w.y);
                *(__half2*)(pw + 2) = __floats2half2_rn(w.z, w.w);
            }
        }
        __syncthreads();

        const __half* Bw = sW + sel * FC_TILE_H;
        #pragma unroll
        for (int kk = 0; kk < 32; kk += 16) {
            uint32_t bf[4][2];
            #pragma unroll
            for (int fn = 0; fn < 4; ++fn) {
                int n = wn2 * 32 + fn * 8 + g;
                bf[fn][0] = *(const uint32_t*)(Bw + n * FC_AST + kk + 2 * t4);
                bf[fn][1] = *(const uint32_t*)(Bw + n * FC_AST + kk + 2 * t4 + 8);
            }
            #pragma unroll
            for (int sp = 0; sp < 2; ++sp) {
                const __half* As = sYh + (sel * 2 + sp) * FC_TILE_H;
                uint32_t a[4][4];
                #pragma unroll
                for (int fm = 0; fm < 4; ++fm) {
                    int m = wm * 64 + fm * 16 + g;
                    a[fm][0] = *(const uint32_t*)(As + m * FC_AST + kk + 2 * t4);
                    a[fm][1] = *(const uint32_t*)(As + (m + 8) * FC_AST + kk + 2 * t4);
                    a[fm][2] = *(const uint32_t*)(As + m * FC_AST + kk + 2 * t4 + 8);
                    a[fm][3] = *(const uint32_t*)(As + (m + 8) * FC_AST + kk + 2 * t4 + 8);
                }
                #pragma unroll
                for (int fm = 0; fm < 4; ++fm)
                    #pragma unroll
                    for (int fn = 0; fn < 4; ++fn)
                        MMAH(d[fm][fn], a[fm], bf[fn]);
            }
        }
    }

    // ---- write h into smem hbuf (stride 260) ----
    __syncthreads();   // all smem tile reads done before overwrite
    const float* bias = sel ? bo : bi;
    const int c2 = t4 * 2;
    #pragma unroll
    for (int fm = 0; fm < 4; ++fm) {
        int lr = wm * 64 + fm * 16 + g;
        #pragma unroll
        for (int fn = 0; fn < 4; ++fn) {
            int cl = wn2 * 32 + fn * 8 + c2;
            int colg = sel * 128 + cl;
            float b0 = 2.f * bias[cl], b1 = 2.f * bias[cl + 1];
            hbuf[lr * 260 + colg]           = d[fm][fn][0] + b0;
            hbuf[lr * 260 + colg + 1]       = d[fm][fn][1] + b1;
            hbuf[(lr + 8) * 260 + colg]     = d[fm][fn][2] + b0;
            hbuf[(lr + 8) * 260 + colg + 1] = d[fm][fn][3] + b1;
        }
    }
    __syncthreads();

    // ---- LayerNorm(256) + exact GELU, 4 threads per row ----
    {
        int row = tid >> 2, p = tid & 3;
        float s = 0.f, s2 = 0.f;
        #pragma unroll
        for (int j = 0; j < 16; ++j) {
            float4 v = *(const float4*)(hbuf + row * 260 + p * 4 + 16 * j);
            s += v.x + v.y + v.z + v.w;
            s2 += v.x * v.x + v.y * v.y + v.z * v.z + v.w * v.w;
        }
        #pragma unroll
        for (int off = 1; off <= 2; off <<= 1) {
            s  += __shfl_xor_sync(0xffffffffu, s,  off);
            s2 += __shfl_xor_sync(0xffffffffu, s2, off);
        }
        float mu  = s * (1.f / DD);
        float var = s2 * (1.f / DD) - mu * mu;
        float rr  = rsqrtf(var + 1e-5f);
        float* outp = (to_mid ? g_xmid : out_ext) + (size_t)(m0 + row) * DD;
        #pragma unroll
        for (int j = 0; j < 16; ++j) {
            int col = p * 4 + 16 * j;
            float4 v = *(const float4*)(hbuf + row * 260 + col);
            float4 o;
            float hn;
            hn = (v.x - mu) * rr * gw[col]     + bw[col];
            o.x = 0.5f * hn * (1.f + erff(hn * 0.70710678118654752f));
            hn = (v.y - mu) * rr * gw[col + 1] + bw[col + 1];
            o.y = 0.5f * hn * (1.f + erff(hn * 0.70710678118654752f));
            hn = (v.z - mu) * rr * gw[col + 2] + bw[col + 2];
            o.z = 0.5f * hn * (1.f + erff(hn * 0.70710678118654752f));
            hn = (v.w - mu) * rr * gw[col + 3] + bw[col + 3];
            o.w = 0.5f * hn * (1.f + erff(hn * 0.70710678118654752f));
            *(float4*)(outp + col) = o;
        }
    }
}

// ---------------- host launcher ----------------
extern "C" void kernel_launch(void* const* d_in, const int* in_sizes, int n_in,
                              void* d_out, int out_size) {
    (void)in_sizes; (void)n_in; (void)out_size;
    const float* x0  = (const float*)d_in[0];
    const float* lat = (const float*)d_in[1];
    const float* dep = (const float*)d_in[2];
    const float* rg  = (const float*)d_in[3];
    const float* Wgi = (const float*)d_in[4];
    const float* bgi = (const float*)d_in[5];
    const float* Wgo = (const float*)d_in[6];
    const float* bgo = (const float*)d_in[7];
    const float* Wi  = (const float*)d_in[8];
    const float* bi  = (const float*)d_in[9];
    const float* Wo  = (const float*)d_in[10];
    const float* bo  = (const float*)d_in[11];
    const float* lng = (const float*)d_in[12];
    const float* lnb = (const float*)d_in[13];
    float* out = (float*)d_out;

    cudaFuncSetAttribute(adj_fused_kernel, cudaFuncAttributeMaxDynamicSharedMemorySize, ADJ_SMEM);
    cudaFuncSetAttribute(fc_ln_kernel,     cudaFuncAttributeMaxDynamicSharedMemorySize, FC_SMEM);

    const int nodeWarpBlocks = (Bq * NN * 32) / 256;   // 2048

    for (int l = 0; l < LL; l++) {
        int use_mid = (l != 0);
        int to_mid  = (l != LL - 1);

        gate_kernel<<<nodeWarpBlocks, 256>>>(x0, use_mid, rg + l * DD);

        dim3 gX(DD / 32, NN / 32, Bq);
        xt_kernel<<<gX, dim3(32, 8)>>>(x0, use_mid);

        dim3 gM(NN / 128, Bq, 2);
        adj_fused_kernel<<<gM, 512, ADJ_SMEM>>>(dep, lat, x0, use_mid,
                                                Wgi + l * DD, bgi + l,
                                                Wgo + l * DD, bgo + l);

        fc_ln_kernel<<<(Bq * NN) / 128, 512, FC_SMEM>>>(
            Wi + (size_t)l * HH * DD, bi + l * HH,
            Wo + (size_t)l * HH * DD, bo + l * HH,
            lng + l * 2 * HH, lnb + l * 2 * HH,
            out, to_mid);
    }
}